// round 13
// baseline (speedup 1.0000x reference)
#include <cuda_runtime.h>
#include <cuda_bf16.h>
#include <math.h>
#include <stdint.h>

// Problem constants
#define BB 2
#define SS 2048
#define DD 1024
#define HH 16
#define DKV 64
#define MS (BB*SS)          // 4096
#define HD (HH*DKV)         // 1024

// ---------------------------------------------------------------------------
// Device scratch (allocation-free)
// ---------------------------------------------------------------------------
__device__ float g_bias[HH*4095];                 // bias[h][rel+2047]
__device__ __nv_bfloat16 g_Xhi[MS*DD], g_Xlo[MS*DD];
__device__ __nv_bfloat16 g_WThi[4][DD*HD], g_WTlo[4][DD*HD];   // WT[n][k]
__device__ __nv_bfloat16 g_Qhi[MS*HD], g_Qlo[MS*HD];
__device__ __nv_bfloat16 g_Khi[MS*HD], g_Klo[MS*HD];
__device__ __nv_bfloat16 g_Vhi[MS*HD], g_Vlo[MS*HD];
__device__ __nv_bfloat16 g_VThi[32*64*2048], g_VTlo[32*64*2048]; // VT[bh][dk][s]
__device__ __nv_bfloat16 g_Chi[MS*HD], g_Clo[MS*HD];

// ---------------------------------------------------------------------------
// Helpers (compute_103 baseline: mma.sync sm_80, ldmatrix sm_75, cp.async sm_80)
// ---------------------------------------------------------------------------
__device__ __forceinline__ void mma16816(float* c, const uint32_t* a,
                                         uint32_t b0, uint32_t b1) {
    asm volatile(
        "mma.sync.aligned.m16n8k16.row.col.f32.bf16.bf16.f32 "
        "{%0,%1,%2,%3}, {%4,%5,%6,%7}, {%8,%9}, {%0,%1,%2,%3};"
        : "+f"(c[0]), "+f"(c[1]), "+f"(c[2]), "+f"(c[3])
        : "r"(a[0]), "r"(a[1]), "r"(a[2]), "r"(a[3]), "r"(b0), "r"(b1));
}
__device__ __forceinline__ void ldsm4(uint32_t* r, uint32_t addr) {
    asm volatile("ldmatrix.sync.aligned.m8n8.x4.shared.b16 {%0,%1,%2,%3}, [%4];"
                 : "=r"(r[0]), "=r"(r[1]), "=r"(r[2]), "=r"(r[3]) : "r"(addr));
}
__device__ __forceinline__ uint32_t packbf(float lo, float hi) {
    __nv_bfloat162 r(__float2bfloat16(lo), __float2bfloat16(hi));
    return *(uint32_t*)&r;
}
__device__ __forceinline__ float bflo(float x) {
    return x - __bfloat162float(__float2bfloat16(x));
}
__device__ __forceinline__ uint32_t smem_u32(const void* p) {
    uint32_t a;
    asm("{ .reg .u64 t; cvta.to.shared.u64 t, %1; cvt.u32.u64 %0, t; }"
        : "=r"(a) : "l"(p));
    return a;
}
__device__ __forceinline__ void cpa16(uint32_t d, const void* s) {
    asm volatile("cp.async.cg.shared.global [%0], [%1], 16;"
                 :: "r"(d), "l"(s) : "memory");
}
__device__ __forceinline__ void cpa4(uint32_t d, const void* s) {
    asm volatile("cp.async.ca.shared.global [%0], [%1], 4;"
                 :: "r"(d), "l"(s) : "memory");
}
#define CP_COMMIT() asm volatile("cp.async.commit_group;" ::: "memory")
#define CP_WAIT1()  asm volatile("cp.async.wait_group 1;" ::: "memory")
#define CP_WAIT0()  asm volatile("cp.async.wait_group 0;" ::: "memory")

// ---------------------------------------------------------------------------
// Bias table
// ---------------------------------------------------------------------------
__global__ void bias_table_kernel(const float* __restrict__ rel_bias) {
    int idx = blockIdx.x * blockDim.x + threadIdx.x;
    if (idx >= HH * 4095) return;
    int h   = idx / 4095;
    int rel = (idx % 4095) - 2047;
    int bucket = (rel > 0) ? 16 : 0;
    int rp = rel < 0 ? -rel : rel;
    int v;
    if (rp < 8) {
        v = rp;
    } else {
        float t = logf((float)rp * 0.125f);
        t = t / 2.772588722239781f;
        t = t * 8.0f;
        v = 8 + (int)t;
        if (v > 15) v = 15;
    }
    g_bias[idx] = rel_bias[(bucket + v) * HH + h];
}

// ---------------------------------------------------------------------------
// fp32 -> bf16 hi/lo split (X)
// ---------------------------------------------------------------------------
__global__ void conv_split(const float* __restrict__ src,
                           __nv_bfloat16* __restrict__ hi,
                           __nv_bfloat16* __restrict__ lo) {
    int i = blockIdx.x * blockDim.x + threadIdx.x;
    float4 v = ((const float4*)src)[i];
    __nv_bfloat162* hp = (__nv_bfloat162*)hi;
    __nv_bfloat162* lp = (__nv_bfloat162*)lo;
    __nv_bfloat16 h0 = __float2bfloat16(v.x), h1 = __float2bfloat16(v.y);
    __nv_bfloat16 h2 = __float2bfloat16(v.z), h3 = __float2bfloat16(v.w);
    hp[2*i]   = __nv_bfloat162(h0, h1);
    hp[2*i+1] = __nv_bfloat162(h2, h3);
    lp[2*i]   = __nv_bfloat162(__float2bfloat16(v.x - __bfloat162float(h0)),
                               __float2bfloat16(v.y - __bfloat162float(h1)));
    lp[2*i+1] = __nv_bfloat162(__float2bfloat16(v.z - __bfloat162float(h2)),
                               __float2bfloat16(v.w - __bfloat162float(h3)));
}

// ---------------------------------------------------------------------------
// Weight transpose + split, all 4 weights in one launch (grid.z picks W)
// ---------------------------------------------------------------------------
__global__ void conv_wt4(const float* __restrict__ W0, const float* __restrict__ W1,
                         const float* __restrict__ W2, const float* __restrict__ W3,
                         __nv_bfloat16* __restrict__ thi_base,
                         __nv_bfloat16* __restrict__ tlo_base) {
    __shared__ float t[32][33];
    int w = blockIdx.z;
    const float* W = (w == 0) ? W0 : (w == 1) ? W1 : (w == 2) ? W2 : W3;
    __nv_bfloat16* thi = thi_base + (size_t)w * DD * HD;
    __nv_bfloat16* tlo = tlo_base + (size_t)w * DD * HD;
    int n0 = blockIdx.x * 32, k0 = blockIdx.y * 32;
    int tx = threadIdx.x, ty = threadIdx.y;
    #pragma unroll
    for (int r = ty; r < 32; r += 8)
        t[r][tx] = W[(k0 + r) * DD + n0 + tx];
    __syncthreads();
    #pragma unroll
    for (int r = ty; r < 32; r += 8) {
        float x = t[tx][r];
        __nv_bfloat16 h = __float2bfloat16(x);
        thi[(n0 + r) * DD + k0 + tx] = h;
        tlo[(n0 + r) * DD + k0 + tx] = __float2bfloat16(x - __bfloat162float(h));
    }
}

// ---------------------------------------------------------------------------
// V transpose to VT[bh][dk][s] (hi/lo), 32x32 smem tiles
// ---------------------------------------------------------------------------
__global__ void conv_vt(const __nv_bfloat16* __restrict__ Vhi,
                        const __nv_bfloat16* __restrict__ Vlo,
                        __nv_bfloat16* __restrict__ VThi,
                        __nv_bfloat16* __restrict__ VTlo) {
    __shared__ __nv_bfloat16 th[32][34], tl[32][34];
    int bh = blockIdx.z, b = bh >> 4, h = bh & 15;
    int s0 = blockIdx.x * 32, dk0 = blockIdx.y * 32;
    int tx = threadIdx.x, ty = threadIdx.y;
    #pragma unroll
    for (int r = ty; r < 32; r += 8) {
        size_t so = (size_t)(b * SS + s0 + r) * HD + h * 64 + dk0 + tx;
        th[r][tx] = Vhi[so];
        tl[r][tx] = Vlo[so];
    }
    __syncthreads();
    #pragma unroll
    for (int r = ty; r < 32; r += 8) {
        size_t dof = (size_t)bh * 64 * SS + (size_t)(dk0 + r) * SS + s0 + tx;
        VThi[dof] = th[tx][r];
        VTlo[dof] = tl[tx][r];
    }
}

// ---------------------------------------------------------------------------
// 3-split bf16 GEMM: R10 layout (KC=64, double-buffered cp.async) + ldmatrix.
// C[4096,1024] = A @ BT^T.  CTA 128x128, 8 warps (2m x 4n), warp tile 64x32.
// stage buf b at offset b*73728: AH+0, AL+18432, BH+36864, BL+55296
// ---------------------------------------------------------------------------
#define GEMM_SMEM 147456

__device__ __forceinline__ void g3_stage(uint32_t smb, int buf,
    const __nv_bfloat16* __restrict__ A0, const __nv_bfloat16* __restrict__ A1,
    const __nv_bfloat16* __restrict__ B0, const __nv_bfloat16* __restrict__ B1,
    int k0, int tid)
{
    uint32_t base = smb + (uint32_t)buf * 73728u;
    #pragma unroll
    for (int i = 0; i < 4; i++) {
        int v = tid + i * 256, row = v >> 3, cw = v & 7;
        size_t so = (size_t)row * 1024 + k0 + cw * 8;
        uint32_t dof = row * 144 + cw * 16;
        cpa16(base + dof,         A0 + so);
        cpa16(base + 18432 + dof, A1 + so);
        cpa16(base + 36864 + dof, B0 + so);
        cpa16(base + 55296 + dof, B1 + so);
    }
    CP_COMMIT();
}

__global__ __launch_bounds__(256) void gemm3(
    const __nv_bfloat16* __restrict__ Ahi, const __nv_bfloat16* __restrict__ Alo,
    const __nv_bfloat16* __restrict__ Bhi, const __nv_bfloat16* __restrict__ Blo,
    float* __restrict__ Cf,
    __nv_bfloat16* __restrict__ Chi, __nv_bfloat16* __restrict__ Clo,
    int mode)
{
    extern __shared__ char sm[];
    uint32_t smb = smem_u32(sm);
    int tid = threadIdx.x, lane = tid & 31, wid = tid >> 5;
    int g = lane >> 2, t4 = lane & 3;
    int wm = wid & 1, wn = wid >> 1;
    int n0 = blockIdx.x * 128, m0 = blockIdx.y * 128;
    uint32_t lb = (lane & 15) * 144 + (lane >> 4) * 16;   // ldmatrix lane offset

    const __nv_bfloat16* A0 = Ahi + (size_t)m0 * 1024;
    const __nv_bfloat16* A1 = Alo + (size_t)m0 * 1024;
    const __nv_bfloat16* B0 = Bhi + (size_t)n0 * 1024;
    const __nv_bfloat16* B1 = Blo + (size_t)n0 * 1024;

    float acc[4][4][4];
    #pragma unroll
    for (int a = 0; a < 4; a++)
        #pragma unroll
        for (int b = 0; b < 4; b++)
            #pragma unroll
            for (int c = 0; c < 4; c++) acc[a][b][c] = 0.f;

    g3_stage(smb, 0, A0, A1, B0, B1, 0, tid);

    for (int c = 0; c < 16; c++) {
        if (c < 15) {
            g3_stage(smb, (c + 1) & 1, A0, A1, B0, B1, (c + 1) * 64, tid);
            CP_WAIT1();
        } else {
            CP_WAIT0();
        }
        __syncthreads();

        uint32_t bp = smb + (c & 1) * 73728u;
        #pragma unroll
        for (int kc = 0; kc < 4; kc++) {
            uint32_t kofs = kc * 32 + lb;
            uint32_t ah[4][4], al[4][4];
            #pragma unroll
            for (int mt = 0; mt < 4; mt++) {
                uint32_t ro = (wm * 64 + mt * 16) * 144 + kofs;
                ldsm4(ah[mt], bp + ro);
                ldsm4(al[mt], bp + 18432 + ro);
            }
            uint32_t bhf[2][4], blf[2][4];
            #pragma unroll
            for (int p = 0; p < 2; p++) {
                uint32_t ro = (wn * 32 + p * 16) * 144 + kofs;
                ldsm4(bhf[p], bp + 36864 + ro);
                ldsm4(blf[p], bp + 55296 + ro);
            }
            #pragma unroll
            for (int nt = 0; nt < 4; nt++) {
                int p = nt >> 1, s = nt & 1;
                uint32_t bh0 = bhf[p][s], bh1 = bhf[p][s + 2];
                uint32_t bl0 = blf[p][s], bl1 = blf[p][s + 2];
                #pragma unroll
                for (int mt = 0; mt < 4; mt++)
                    mma16816(acc[mt][nt], ah[mt], bh0, bh1);
                #pragma unroll
                for (int mt = 0; mt < 4; mt++)
                    mma16816(acc[mt][nt], ah[mt], bl0, bl1);
                #pragma unroll
                for (int mt = 0; mt < 4; mt++)
                    mma16816(acc[mt][nt], al[mt], bh0, bh1);
            }
        }
        __syncthreads();
    }

    #pragma unroll
    for (int mt = 0; mt < 4; mt++) {
        #pragma unroll
        for (int nt = 0; nt < 4; nt++) {
            int row = m0 + wm * 64 + mt * 16 + g;
            int col = n0 + wn * 32 + nt * 8 + t4 * 2;
            float* c = acc[mt][nt];
            if (mode) {
                *(float2*)(Cf + (size_t)row * 1024 + col)       = make_float2(c[0], c[1]);
                *(float2*)(Cf + (size_t)(row + 8) * 1024 + col) = make_float2(c[2], c[3]);
            } else {
                size_t o0 = (size_t)row * 1024 + col;
                size_t o8 = (size_t)(row + 8) * 1024 + col;
                *(uint32_t*)(Chi + o0) = packbf(c[0], c[1]);
                *(uint32_t*)(Clo + o0) = packbf(bflo(c[0]), bflo(c[1]));
                *(uint32_t*)(Chi + o8) = packbf(c[2], c[3]);
                *(uint32_t*)(Clo + o8) = packbf(bflo(c[2]), bflo(c[3]));
            }
        }
    }
}

// ---------------------------------------------------------------------------
// MMA flash attention: R10 structure (separate Q/K/V, stride 1024, per-kc Q
// fragment loads — no hoist) + ldmatrix fragment loads.
// smem: Q[0,36864) | K buf b @36864+b*36864 (hi, lo+18432)
//       V buf b @110592+b*34816 (hi, lo+17408; 64 rows x 272B)
//       bias buf b @180224+b*1024
// ---------------------------------------------------------------------------
#define F_K 36864
#define F_V 110592
#define F_B 180224
#define FLASH_SMEM 182272
#define VSTR 272

__device__ __forceinline__ void fl_stage(uint32_t smb, int buf,
    const __nv_bfloat16* __restrict__ Kh, const __nv_bfloat16* __restrict__ Kl,
    const __nv_bfloat16* __restrict__ Vh, const __nv_bfloat16* __restrict__ Vl,
    const float* __restrict__ bsrc, int tid)
{
    uint32_t kb = smb + F_K + (uint32_t)buf * 36864u;
    #pragma unroll
    for (int i = 0; i < 4; i++) {
        int v = tid + i * 256, row = v >> 3, cw = v & 7;
        size_t so = (size_t)row * HD + cw * 8;
        uint32_t dof = row * 144 + cw * 16;
        cpa16(kb + dof,         Kh + so);
        cpa16(kb + 18432 + dof, Kl + so);
    }
    uint32_t vb = smb + F_V + (uint32_t)buf * 34816u;
    #pragma unroll
    for (int i = 0; i < 4; i++) {
        int v = tid + i * 256, row = v >> 4, cw = v & 15;   // row<64
        size_t so = (size_t)row * SS + cw * 8;
        uint32_t dof = row * VSTR + cw * 16;
        cpa16(vb + dof,         Vh + so);
        cpa16(vb + 17408 + dof, Vl + so);
    }
    if (tid < 255) cpa4(smb + F_B + (uint32_t)buf * 1024u + tid * 4, bsrc + tid);
    CP_COMMIT();
}

__global__ __launch_bounds__(256) void flash_mma(
    const __nv_bfloat16* __restrict__ Qhi, const __nv_bfloat16* __restrict__ Qlo,
    const __nv_bfloat16* __restrict__ Khi, const __nv_bfloat16* __restrict__ Klo,
    const __nv_bfloat16* __restrict__ VThi, const __nv_bfloat16* __restrict__ VTlo,
    __nv_bfloat16* __restrict__ Chi, __nv_bfloat16* __restrict__ Clo)
{
    extern __shared__ char sm[];
    uint32_t smb = smem_u32(sm);
    int tid = threadIdx.x, lane = tid & 31, wid = tid >> 5;
    int g = lane >> 2, t4 = lane & 3;
    int qt = blockIdx.x;             // 0..15
    int bh = blockIdx.y;             // 0..31
    int b = bh >> 4, h = bh & 15;
    uint32_t lb  = (lane & 15) * 144 + (lane >> 4) * 16;
    uint32_t lbv = (lane & 15) * VSTR + (lane >> 4) * 16;

    size_t qbase = ((size_t)b * SS + qt * 128) * HD + h * 64;
    const __nv_bfloat16* Kb  = Khi + ((size_t)b * SS) * HD + h * 64;
    const __nv_bfloat16* Kbl = Klo + ((size_t)b * SS) * HD + h * 64;
    const __nv_bfloat16* Vb  = VThi + (size_t)bh * 64 * SS;
    const __nv_bfloat16* Vbl = VTlo + (size_t)bh * 64 * SS;
    const float* btab = g_bias + h * 4095 + 2047;

    // Stage Q tile hi/lo (plain loads, once)
    #pragma unroll
    for (int i = 0; i < 4; i++) {
        int v = tid + i * 256, row = v >> 3, cw = v & 7;
        size_t so = qbase + (size_t)row * HD + cw * 8;
        uint32_t dof = row * 144 + cw * 16;
        *(uint4*)(sm + dof)         = *(const uint4*)(Qhi + so);
        *(uint4*)(sm + 18432 + dof) = *(const uint4*)(Qlo + so);
    }

    fl_stage(smb, 0, Kb, Kbl, Vb, Vbl, btab - qt * 128 - 127, tid);

    float m0 = -1e30f, m1 = -1e30f, l0 = 0.f, l1 = 0.f;
    float oa[8][4];
    #pragma unroll
    for (int nt = 0; nt < 8; nt++)
        #pragma unroll
        for (int c = 0; c < 4; c++) oa[nt][c] = 0.f;

    for (int kt = 0; kt < 16; kt++) {
        if (kt < 15) {
            int kn = kt + 1;
            fl_stage(smb, kn & 1,
                     Kb + (size_t)kn * 128 * HD, Kbl + (size_t)kn * 128 * HD,
                     Vb + kn * 128, Vbl + kn * 128,
                     btab + (kn - qt) * 128 - 127, tid);
            CP_WAIT1();
        } else {
            CP_WAIT0();
        }
        __syncthreads();

        uint32_t kp = smb + F_K + (kt & 1) * 36864u;
        uint32_t vp = smb + F_V + (kt & 1) * 34816u;
        float* bsm = (float*)(sm + F_B + (kt & 1) * 1024);

        // ---- S = Q K^T (3-split), warp strip 16 x 128, ldmatrix frags ----
        float sa[16][4];
        #pragma unroll
        for (int nt = 0; nt < 16; nt++)
            #pragma unroll
            for (int c = 0; c < 4; c++) sa[nt][c] = 0.f;

        #pragma unroll
        for (int kc = 0; kc < 4; kc++) {
            uint32_t kofs = kc * 32 + lb;
            uint32_t qh[4], ql[4];
            {
                uint32_t ro = (wid * 16) * 144 + kofs;
                ldsm4(qh, smb + ro);
                ldsm4(ql, smb + 18432 + ro);
            }
            #pragma unroll
            for (int p = 0; p < 8; p++) {
                uint32_t ro = (p * 16) * 144 + kofs;
                uint32_t khf[4], klf[4];
                ldsm4(khf, kp + ro);
                ldsm4(klf, kp + 18432 + ro);
                #pragma unroll
                for (int s = 0; s < 2; s++) {
                    int nt = 2 * p + s;
                    mma16816(sa[nt], qh, khf[s], khf[s + 2]);
                    mma16816(sa[nt], qh, klf[s], klf[s + 2]);
                    mma16816(sa[nt], ql, khf[s], khf[s + 2]);
                }
            }
        }

        // ---- bias + online softmax ----
        float m0n = m0, m1n = m1;
        #pragma unroll
        for (int nt = 0; nt < 16; nt++) {
            int base = nt * 8 + t4 * 2 - (wid * 16 + g) + 127;
            sa[nt][0] += bsm[base];
            sa[nt][1] += bsm[base + 1];
            sa[nt][2] += bsm[base - 8];
            sa[nt][3] += bsm[base - 7];
            m0n = fmaxf(m0n, fmaxf(sa[nt][0], sa[nt][1]));
            m1n = fmaxf(m1n, fmaxf(sa[nt][2], sa[nt][3]));
        }
        m0n = fmaxf(m0n, __shfl_xor_sync(0xffffffffu, m0n, 1));
        m0n = fmaxf(m0n, __shfl_xor_sync(0xffffffffu, m0n, 2));
        m1n = fmaxf(m1n, __shfl_xor_sync(0xffffffffu, m1n, 1));
        m1n = fmaxf(m1n, __shfl_xor_sync(0xffffffffu, m1n, 2));

        float sc0 = __expf(m0 - m0n), sc1 = __expf(m1 - m1n);
        float rs0 = 0.f, rs1 = 0.f;
        #pragma unroll
        for (int nt = 0; nt < 16; nt++) {
            sa[nt][0] = __expf(sa[nt][0] - m0n);
            sa[nt][1] = __expf(sa[nt][1] - m0n);
            sa[nt][2] = __expf(sa[nt][2] - m1n);
            sa[nt][3] = __expf(sa[nt][3] - m1n);
            rs0 += sa[nt][0] + sa[nt][1];
            rs1 += sa[nt][2] + sa[nt][3];
        }
        rs0 += __shfl_xor_sync(0xffffffffu, rs0, 1);
        rs0 += __shfl_xor_sync(0xffffffffu, rs0, 2);
        rs1 += __shfl_xor_sync(0xffffffffu, rs1, 1);
        rs1 += __shfl_xor_sync(0xffffffffu, rs1, 2);
        l0 = l0 * sc0 + rs0;
        l1 = l1 * sc1 + rs1;
        m0 = m0n; m1 = m1n;
        #pragma unroll
        for (int nt = 0; nt < 8; nt++) {
            oa[nt][0] *= sc0; oa[nt][1] *= sc0;
            oa[nt][2] *= sc1; oa[nt][3] *= sc1;
        }

        // ---- O += P V (3-split; P fragments direct from S acc) ----
        #pragma unroll
        for (int kc = 0; kc < 8; kc++) {
            float* pA = sa[2 * kc];
            float* pB = sa[2 * kc + 1];
            uint32_t ph[4], pl[4];
            ph[0] = packbf(pA[0], pA[1]);
            ph[1] = packbf(pA[2], pA[3]);
            ph[2] = packbf(pB[0], pB[1]);
            ph[3] = packbf(pB[2], pB[3]);
            pl[0] = packbf(bflo(pA[0]), bflo(pA[1]));
            pl[1] = packbf(bflo(pA[2]), bflo(pA[3]));
            pl[2] = packbf(bflo(pB[0]), bflo(pB[1]));
            pl[3] = packbf(bflo(pB[2]), bflo(pB[3]));
            uint32_t kofs = kc * 32 + lbv;
            #pragma unroll
            for (int p = 0; p < 4; p++) {
                uint32_t ro = (p * 16) * VSTR + kofs;
                uint32_t vhf[4], vlf[4];
                ldsm4(vhf, vp + ro);
                ldsm4(vlf, vp + 17408 + ro);
                #pragma unroll
                for (int s = 0; s < 2; s++) {
                    int nt = 2 * p + s;
                    mma16816(oa[nt], ph, vhf[s], vhf[s + 2]);
                    mma16816(oa[nt], ph, vlf[s], vlf[s + 2]);
                    mma16816(oa[nt], pl, vhf[s], vhf[s + 2]);
                }
            }
        }
        __syncthreads();
    }

    // ---- normalize, split, store ctx ----
    float inv0 = 1.f / l0, inv1 = 1.f / l1;
    #pragma unroll
    for (int nt = 0; nt < 8; nt++) {
        size_t o0 = qbase + (size_t)(wid * 16 + g) * HD + nt * 8 + t4 * 2;
        size_t o8 = o0 + 8 * HD;
        float v0 = oa[nt][0] * inv0, v1 = oa[nt][1] * inv0;
        float v2 = oa[nt][2] * inv1, v3 = oa[nt][3] * inv1;
        *(uint32_t*)(Chi + o0) = packbf(v0, v1);
        *(uint32_t*)(Clo + o0) = packbf(bflo(v0), bflo(v1));
        *(uint32_t*)(Chi + o8) = packbf(v2, v3);
        *(uint32_t*)(Clo + o8) = packbf(bflo(v2), bflo(v3));
    }
}

// ---------------------------------------------------------------------------
// Launch
// ---------------------------------------------------------------------------
extern "C" void kernel_launch(void* const* d_in, const int* in_sizes, int n_in,
                              void* d_out, int out_size) {
    const float* X  = (const float*)d_in[0];
    const float* Wq = (const float*)d_in[1];
    const float* Wk = (const float*)d_in[2];
    const float* Wv = (const float*)d_in[3];
    const float* Wo = (const float*)d_in[4];
    const float* rb = (const float*)d_in[5];
    float* out = (float*)d_out;

    __nv_bfloat16 *Xhi, *Xlo, *WThi, *WTlo;
    __nv_bfloat16 *Qhi, *Qlo, *Khi, *Klo, *Vhi, *Vlo, *VThi, *VTlo, *Chi, *Clo;
    cudaGetSymbolAddress((void**)&Xhi, g_Xhi);
    cudaGetSymbolAddress((void**)&Xlo, g_Xlo);
    cudaGetSymbolAddress((void**)&WThi, g_WThi);
    cudaGetSymbolAddress((void**)&WTlo, g_WTlo);
    cudaGetSymbolAddress((void**)&Qhi, g_Qhi);
    cudaGetSymbolAddress((void**)&Qlo, g_Qlo);
    cudaGetSymbolAddress((void**)&Khi, g_Khi);
    cudaGetSymbolAddress((void**)&Klo, g_Klo);
    cudaGetSymbolAddress((void**)&Vhi, g_Vhi);
    cudaGetSymbolAddress((void**)&Vlo, g_Vlo);
    cudaGetSymbolAddress((void**)&VThi, g_VThi);
    cudaGetSymbolAddress((void**)&VTlo, g_VTlo);
    cudaGetSymbolAddress((void**)&Chi, g_Chi);
    cudaGetSymbolAddress((void**)&Clo, g_Clo);

    cudaFuncSetAttribute(gemm3,
                         cudaFuncAttributeMaxDynamicSharedMemorySize, GEMM_SMEM);
    cudaFuncSetAttribute(flash_mma,
                         cudaFuncAttributeMaxDynamicSharedMemorySize, FLASH_SMEM);

    bias_table_kernel<<<(HH * 4095 + 255) / 256, 256>>>(rb);
    conv_split<<<(MS * DD / 4) / 256, 256>>>(X, Xhi, Xlo);
    conv_wt4<<<dim3(DD / 32, DD / 32, 4), dim3(32, 8)>>>(Wq, Wk, Wv, Wo, WThi, WTlo);

    dim3 gg(HD / 128, MS / 128);   // (8, 32)
    gemm3<<<gg, 256, GEMM_SMEM>>>(Xhi, Xlo, WThi, WTlo,
                                  nullptr, Qhi, Qlo, 0);
    gemm3<<<gg, 256, GEMM_SMEM>>>(Xhi, Xlo, WThi + (size_t)1 * DD * HD, WTlo + (size_t)1 * DD * HD,
                                  nullptr, Khi, Klo, 0);
    gemm3<<<gg, 256, GEMM_SMEM>>>(Xhi, Xlo, WThi + (size_t)2 * DD * HD, WTlo + (size_t)2 * DD * HD,
                                  nullptr, Vhi, Vlo, 0);

    conv_vt<<<dim3(SS / 32, 2, 32), dim3(32, 8)>>>(Vhi, Vlo, VThi, VTlo);

    flash_mma<<<dim3(SS / 128, BB * HH), 256, FLASH_SMEM>>>(
        Qhi, Qlo, Khi, Klo, VThi, VTlo, Chi, Clo);

    gemm3<<<gg, 256, GEMM_SMEM>>>(Chi, Clo, WThi + (size_t)3 * DD * HD, WTlo + (size_t)3 * DD * HD,
                                  out, nullptr, nullptr, 1);
}

// round 14
// speedup vs baseline: 1.1514x; 1.1514x over previous
#include <cuda_runtime.h>
#include <cuda_fp16.h>
#include <math.h>
#include <stdint.h>

// Problem constants
#define BB 2
#define SS 2048
#define DD 1024
#define HH 16
#define DKV 64
#define MS (BB*SS)          // 4096
#define HD (HH*DKV)         // 1024

// ---------------------------------------------------------------------------
// Device scratch (allocation-free) — fp16 hi/lo splits
// ---------------------------------------------------------------------------
__device__ float g_bias[HH*4095];                 // bias[h][rel+2047]
__device__ __half g_Xhi[MS*DD], g_Xlo[MS*DD];
__device__ __half g_WThi[4][DD*HD], g_WTlo[4][DD*HD];   // WT[n][k]
__device__ __half g_Qhi[MS*HD], g_Qlo[MS*HD];
__device__ __half g_Khi[MS*HD], g_Klo[MS*HD];
__device__ __half g_Vhi[MS*HD], g_Vlo[MS*HD];
__device__ __half g_VThi[32*64*2048], g_VTlo[32*64*2048]; // VT[bh][dk][s]
__device__ __half g_Chi[MS*HD], g_Clo[MS*HD];

// ---------------------------------------------------------------------------
// Helpers (compute_103 baseline: mma.sync sm_80, cp.async sm_80)
// ---------------------------------------------------------------------------
// Main term: f16 operands, f32 accumulator (rt assumed 16)
__device__ __forceinline__ void mma16816(float* c, const uint32_t* a,
                                         uint32_t b0, uint32_t b1) {
    asm volatile(
        "mma.sync.aligned.m16n8k16.row.col.f32.f16.f16.f32 "
        "{%0,%1,%2,%3}, {%4,%5,%6,%7}, {%8,%9}, {%0,%1,%2,%3};"
        : "+f"(c[0]), "+f"(c[1]), "+f"(c[2]), "+f"(c[3])
        : "r"(a[0]), "r"(a[1]), "r"(a[2]), "r"(a[3]), "r"(b0), "r"(b1));
}
// Correction terms: f16 accumulator (rt hoped 8 = 2x rate)
__device__ __forceinline__ void mma16816h(uint32_t* c, const uint32_t* a,
                                          uint32_t b0, uint32_t b1) {
    asm volatile(
        "mma.sync.aligned.m16n8k16.row.col.f16.f16.f16.f16 "
        "{%0,%1}, {%2,%3,%4,%5}, {%6,%7}, {%0,%1};"
        : "+r"(c[0]), "+r"(c[1])
        : "r"(a[0]), "r"(a[1]), "r"(a[2]), "r"(a[3]), "r"(b0), "r"(b1));
}
// Fold f16x2 correction pair into fp32 acc quad (layout-identical mapping)
__device__ __forceinline__ void fold2(float* c, const uint32_t* h) {
    __half2 x0 = *(const __half2*)&h[0];
    __half2 x1 = *(const __half2*)&h[1];
    c[0] += __low2float(x0); c[1] += __high2float(x0);
    c[2] += __low2float(x1); c[3] += __high2float(x1);
}
__device__ __forceinline__ uint32_t packhf(float lo, float hi) {
    __half2 r = __floats2half2_rn(lo, hi);   // .x = lo
    return *(uint32_t*)&r;
}
__device__ __forceinline__ float hflo(float x) {
    return x - __half2float(__float2half_rn(x));
}
__device__ __forceinline__ uint32_t smem_u32(const void* p) {
    uint32_t a;
    asm("{ .reg .u64 t; cvta.to.shared.u64 t, %1; cvt.u32.u64 %0, t; }"
        : "=r"(a) : "l"(p));
    return a;
}
__device__ __forceinline__ void cpa16(uint32_t d, const void* s) {
    asm volatile("cp.async.cg.shared.global [%0], [%1], 16;"
                 :: "r"(d), "l"(s) : "memory");
}
__device__ __forceinline__ void cpa4(uint32_t d, const void* s) {
    asm volatile("cp.async.ca.shared.global [%0], [%1], 4;"
                 :: "r"(d), "l"(s) : "memory");
}
#define CP_COMMIT() asm volatile("cp.async.commit_group;" ::: "memory")
#define CP_WAIT1()  asm volatile("cp.async.wait_group 1;" ::: "memory")
#define CP_WAIT0()  asm volatile("cp.async.wait_group 0;" ::: "memory")

// ---------------------------------------------------------------------------
// Bias table
// ---------------------------------------------------------------------------
__global__ void bias_table_kernel(const float* __restrict__ rel_bias) {
    int idx = blockIdx.x * blockDim.x + threadIdx.x;
    if (idx >= HH * 4095) return;
    int h   = idx / 4095;
    int rel = (idx % 4095) - 2047;
    int bucket = (rel > 0) ? 16 : 0;
    int rp = rel < 0 ? -rel : rel;
    int v;
    if (rp < 8) {
        v = rp;
    } else {
        float t = logf((float)rp * 0.125f);
        t = t / 2.772588722239781f;
        t = t * 8.0f;
        v = 8 + (int)t;
        if (v > 15) v = 15;
    }
    g_bias[idx] = rel_bias[(bucket + v) * HH + h];
}

// ---------------------------------------------------------------------------
// fp32 -> fp16 hi/lo split (X)
// ---------------------------------------------------------------------------
__global__ void conv_split(const float* __restrict__ src,
                           __half* __restrict__ hi,
                           __half* __restrict__ lo) {
    int i = blockIdx.x * blockDim.x + threadIdx.x;
    float4 v = ((const float4*)src)[i];
    __half2* hp = (__half2*)hi;
    __half2* lp = (__half2*)lo;
    float h0 = __half2float(__float2half_rn(v.x));
    float h1 = __half2float(__float2half_rn(v.y));
    float h2 = __half2float(__float2half_rn(v.z));
    float h3 = __half2float(__float2half_rn(v.w));
    hp[2*i]   = __floats2half2_rn(v.x, v.y);
    hp[2*i+1] = __floats2half2_rn(v.z, v.w);
    lp[2*i]   = __floats2half2_rn(v.x - h0, v.y - h1);
    lp[2*i+1] = __floats2half2_rn(v.z - h2, v.w - h3);
}

// ---------------------------------------------------------------------------
// Weight transpose + split, all 4 weights in one launch (grid.z picks W)
// ---------------------------------------------------------------------------
__global__ void conv_wt4(const float* __restrict__ W0, const float* __restrict__ W1,
                         const float* __restrict__ W2, const float* __restrict__ W3,
                         __half* __restrict__ thi_base,
                         __half* __restrict__ tlo_base) {
    __shared__ float t[32][33];
    int w = blockIdx.z;
    const float* W = (w == 0) ? W0 : (w == 1) ? W1 : (w == 2) ? W2 : W3;
    __half* thi = thi_base + (size_t)w * DD * HD;
    __half* tlo = tlo_base + (size_t)w * DD * HD;
    int n0 = blockIdx.x * 32, k0 = blockIdx.y * 32;
    int tx = threadIdx.x, ty = threadIdx.y;
    #pragma unroll
    for (int r = ty; r < 32; r += 8)
        t[r][tx] = W[(k0 + r) * DD + n0 + tx];
    __syncthreads();
    #pragma unroll
    for (int r = ty; r < 32; r += 8) {
        float x = t[tx][r];
        __half h = __float2half_rn(x);
        thi[(n0 + r) * DD + k0 + tx] = h;
        tlo[(n0 + r) * DD + k0 + tx] = __float2half_rn(x - __half2float(h));
    }
}

// ---------------------------------------------------------------------------
// V transpose to VT[bh][dk][s] (hi/lo), 32x32 smem tiles
// ---------------------------------------------------------------------------
__global__ void conv_vt(const __half* __restrict__ Vhi,
                        const __half* __restrict__ Vlo,
                        __half* __restrict__ VThi,
                        __half* __restrict__ VTlo) {
    __shared__ __half th[32][34], tl[32][34];
    int bh = blockIdx.z, b = bh >> 4, h = bh & 15;
    int s0 = blockIdx.x * 32, dk0 = blockIdx.y * 32;
    int tx = threadIdx.x, ty = threadIdx.y;
    #pragma unroll
    for (int r = ty; r < 32; r += 8) {
        size_t so = (size_t)(b * SS + s0 + r) * HD + h * 64 + dk0 + tx;
        th[r][tx] = Vhi[so];
        tl[r][tx] = Vlo[so];
    }
    __syncthreads();
    #pragma unroll
    for (int r = ty; r < 32; r += 8) {
        size_t dof = (size_t)bh * 64 * SS + (size_t)(dk0 + r) * SS + s0 + tx;
        VThi[dof] = th[tx][r];
        VTlo[dof] = tl[tx][r];
    }
}

// ---------------------------------------------------------------------------
// 3-split fp16 GEMM (R10 structure: KC=64, double-buffered cp.async, LDS.32
// fragment loads). Main hi*hi -> f32 acc; corrections hi*lo, lo*hi -> f16 acc.
// stage buf b at offset b*73728: AH+0, AL+18432, BH+36864, BL+55296
// ---------------------------------------------------------------------------
#define GEMM_SMEM 147456

__device__ __forceinline__ void g3_stage(uint32_t smb, int buf,
    const __half* __restrict__ A0, const __half* __restrict__ A1,
    const __half* __restrict__ B0, const __half* __restrict__ B1,
    int k0, int tid)
{
    uint32_t base = smb + (uint32_t)buf * 73728u;
    #pragma unroll
    for (int i = 0; i < 4; i++) {
        int v = tid + i * 256, row = v >> 3, cw = v & 7;
        size_t so = (size_t)row * 1024 + k0 + cw * 8;
        uint32_t dof = row * 144 + cw * 16;
        cpa16(base + dof,         A0 + so);
        cpa16(base + 18432 + dof, A1 + so);
        cpa16(base + 36864 + dof, B0 + so);
        cpa16(base + 55296 + dof, B1 + so);
    }
    CP_COMMIT();
}

__global__ __launch_bounds__(256) void gemm3(
    const __half* __restrict__ Ahi, const __half* __restrict__ Alo,
    const __half* __restrict__ Bhi, const __half* __restrict__ Blo,
    float* __restrict__ Cf,
    __half* __restrict__ Chi, __half* __restrict__ Clo,
    int mode)
{
    extern __shared__ char sm[];
    uint32_t smb = smem_u32(sm);
    int tid = threadIdx.x, lane = tid & 31, wid = tid >> 5;
    int g = lane >> 2, t4 = lane & 3;
    int wm = wid & 1, wn = wid >> 1;
    int n0 = blockIdx.x * 128, m0 = blockIdx.y * 128;

    const __half* A0 = Ahi + (size_t)m0 * 1024;
    const __half* A1 = Alo + (size_t)m0 * 1024;
    const __half* B0 = Bhi + (size_t)n0 * 1024;
    const __half* B1 = Blo + (size_t)n0 * 1024;

    float acc[4][4][4];
    uint32_t acc16[4][4][2];
    #pragma unroll
    for (int a = 0; a < 4; a++)
        #pragma unroll
        for (int b = 0; b < 4; b++) {
            #pragma unroll
            for (int c = 0; c < 4; c++) acc[a][b][c] = 0.f;
            acc16[a][b][0] = 0u; acc16[a][b][1] = 0u;
        }

    g3_stage(smb, 0, A0, A1, B0, B1, 0, tid);

    for (int c = 0; c < 16; c++) {
        if (c < 15) {
            g3_stage(smb, (c + 1) & 1, A0, A1, B0, B1, (c + 1) * 64, tid);
            CP_WAIT1();
        } else {
            CP_WAIT0();
        }
        __syncthreads();

        char* bp = sm + (c & 1) * 73728;
        #pragma unroll
        for (int kc = 0; kc < 4; kc++) {
            uint32_t ah[4][4], al[4][4];
            #pragma unroll
            for (int mt = 0; mt < 4; mt++) {
                uint32_t o  = (wm * 64 + mt * 16 + g) * 144 + kc * 32 + t4 * 4;
                uint32_t o8 = o + 8 * 144;
                ah[mt][0] = *(uint32_t*)(bp + o);
                ah[mt][1] = *(uint32_t*)(bp + o8);
                ah[mt][2] = *(uint32_t*)(bp + o + 16);
                ah[mt][3] = *(uint32_t*)(bp + o8 + 16);
                al[mt][0] = *(uint32_t*)(bp + 18432 + o);
                al[mt][1] = *(uint32_t*)(bp + 18432 + o8);
                al[mt][2] = *(uint32_t*)(bp + 18432 + o + 16);
                al[mt][3] = *(uint32_t*)(bp + 18432 + o8 + 16);
            }
            #pragma unroll
            for (int nt = 0; nt < 4; nt++) {
                uint32_t o = (wn * 32 + nt * 8 + g) * 144 + kc * 32 + t4 * 4;
                uint32_t bh0 = *(uint32_t*)(bp + 36864 + o);
                uint32_t bh1 = *(uint32_t*)(bp + 36864 + o + 16);
                uint32_t bl0 = *(uint32_t*)(bp + 55296 + o);
                uint32_t bl1 = *(uint32_t*)(bp + 55296 + o + 16);
                #pragma unroll
                for (int mt = 0; mt < 4; mt++)
                    mma16816(acc[mt][nt], ah[mt], bh0, bh1);
                #pragma unroll
                for (int mt = 0; mt < 4; mt++)
                    mma16816h(acc16[mt][nt], ah[mt], bl0, bl1);
                #pragma unroll
                for (int mt = 0; mt < 4; mt++)
                    mma16816h(acc16[mt][nt], al[mt], bh0, bh1);
            }
        }
        __syncthreads();
    }

    #pragma unroll
    for (int mt = 0; mt < 4; mt++) {
        #pragma unroll
        for (int nt = 0; nt < 4; nt++) {
            int row = m0 + wm * 64 + mt * 16 + g;
            int col = n0 + wn * 32 + nt * 8 + t4 * 2;
            float* c = acc[mt][nt];
            fold2(c, acc16[mt][nt]);
            if (mode) {
                *(float2*)(Cf + (size_t)row * 1024 + col)       = make_float2(c[0], c[1]);
                *(float2*)(Cf + (size_t)(row + 8) * 1024 + col) = make_float2(c[2], c[3]);
            } else {
                size_t o0 = (size_t)row * 1024 + col;
                size_t o8 = (size_t)(row + 8) * 1024 + col;
                *(uint32_t*)(Chi + o0) = packhf(c[0], c[1]);
                *(uint32_t*)(Clo + o0) = packhf(hflo(c[0]), hflo(c[1]));
                *(uint32_t*)(Chi + o8) = packhf(c[2], c[3]);
                *(uint32_t*)(Clo + o8) = packhf(hflo(c[2]), hflo(c[3]));
            }
        }
    }
}

// ---------------------------------------------------------------------------
// MMA flash attention (R10 structure) — fp16 splits; main terms f32-acc,
// corrections f16-acc folded per k-tile.
// smem: Q[0,36864) | K buf b @36864+b*36864 (hi, lo+18432)
//       V buf b @110592+b*34816 (hi, lo+17408; 64 rows x 272B)
//       bias buf b @180224+b*1024
// ---------------------------------------------------------------------------
#define F_K 36864
#define F_V 110592
#define F_B 180224
#define FLASH_SMEM 182272
#define VSTR 272

__device__ __forceinline__ void fl_stage(uint32_t smb, int buf,
    const __half* __restrict__ Kh, const __half* __restrict__ Kl,
    const __half* __restrict__ Vh, const __half* __restrict__ Vl,
    const float* __restrict__ bsrc, int tid)
{
    uint32_t kb = smb + F_K + (uint32_t)buf * 36864u;
    #pragma unroll
    for (int i = 0; i < 4; i++) {
        int v = tid + i * 256, row = v >> 3, cw = v & 7;
        size_t so = (size_t)row * HD + cw * 8;
        uint32_t dof = row * 144 + cw * 16;
        cpa16(kb + dof,         Kh + so);
        cpa16(kb + 18432 + dof, Kl + so);
    }
    uint32_t vb = smb + F_V + (uint32_t)buf * 34816u;
    #pragma unroll
    for (int i = 0; i < 4; i++) {
        int v = tid + i * 256, row = v >> 4, cw = v & 15;   // row<64
        size_t so = (size_t)row * SS + cw * 8;
        uint32_t dof = row * VSTR + cw * 16;
        cpa16(vb + dof,         Vh + so);
        cpa16(vb + 17408 + dof, Vl + so);
    }
    if (tid < 255) cpa4(smb + F_B + (uint32_t)buf * 1024u + tid * 4, bsrc + tid);
    CP_COMMIT();
}

__global__ __launch_bounds__(256) void flash_mma(
    const __half* __restrict__ Qhi, const __half* __restrict__ Qlo,
    const __half* __restrict__ Khi, const __half* __restrict__ Klo,
    const __half* __restrict__ VThi, const __half* __restrict__ VTlo,
    __half* __restrict__ Chi, __half* __restrict__ Clo)
{
    extern __shared__ char sm[];
    uint32_t smb = smem_u32(sm);
    int tid = threadIdx.x, lane = tid & 31, wid = tid >> 5;
    int g = lane >> 2, t4 = lane & 3;
    int qt = blockIdx.x;             // 0..15
    int bh = blockIdx.y;             // 0..31
    int b = bh >> 4, h = bh & 15;

    size_t qbase = ((size_t)b * SS + qt * 128) * HD + h * 64;
    const __half* Kb  = Khi + ((size_t)b * SS) * HD + h * 64;
    const __half* Kbl = Klo + ((size_t)b * SS) * HD + h * 64;
    const __half* Vb  = VThi + (size_t)bh * 64 * SS;
    const __half* Vbl = VTlo + (size_t)bh * 64 * SS;
    const float* btab = g_bias + h * 4095 + 2047;

    // Stage Q tile hi/lo (plain loads, once)
    #pragma unroll
    for (int i = 0; i < 4; i++) {
        int v = tid + i * 256, row = v >> 3, cw = v & 7;
        size_t so = qbase + (size_t)row * HD + cw * 8;
        uint32_t dof = row * 144 + cw * 16;
        *(uint4*)(sm + dof)         = *(const uint4*)(Qhi + so);
        *(uint4*)(sm + 18432 + dof) = *(const uint4*)(Qlo + so);
    }

    fl_stage(smb, 0, Kb, Kbl, Vb, Vbl, btab - qt * 128 - 127, tid);

    float m0 = -1e30f, m1 = -1e30f, l0 = 0.f, l1 = 0.f;
    float oa[8][4];
    #pragma unroll
    for (int nt = 0; nt < 8; nt++)
        #pragma unroll
        for (int c = 0; c < 4; c++) oa[nt][c] = 0.f;

    for (int kt = 0; kt < 16; kt++) {
        if (kt < 15) {
            int kn = kt + 1;
            fl_stage(smb, kn & 1,
                     Kb + (size_t)kn * 128 * HD, Kbl + (size_t)kn * 128 * HD,
                     Vb + kn * 128, Vbl + kn * 128,
                     btab + (kn - qt) * 128 - 127, tid);
            CP_WAIT1();
        } else {
            CP_WAIT0();
        }
        __syncthreads();

        char* kp = sm + F_K + (kt & 1) * 36864;
        char* vp = sm + F_V + (kt & 1) * 34816;
        float* bsm = (float*)(sm + F_B + (kt & 1) * 1024);

        // ---- S = Q K^T (main f32-acc + corrections f16-acc) ----
        float sa[16][4];
        uint32_t sa16[16][2];
        #pragma unroll
        for (int nt = 0; nt < 16; nt++) {
            #pragma unroll
            for (int c = 0; c < 4; c++) sa[nt][c] = 0.f;
            sa16[nt][0] = 0u; sa16[nt][1] = 0u;
        }

        #pragma unroll
        for (int kc = 0; kc < 4; kc++) {
            uint32_t qh[4], ql[4];
            uint32_t o  = (wid * 16 + g) * 144 + kc * 32 + t4 * 4;
            uint32_t o8 = o + 8 * 144;
            qh[0] = *(uint32_t*)(sm + o);
            qh[1] = *(uint32_t*)(sm + o8);
            qh[2] = *(uint32_t*)(sm + o + 16);
            qh[3] = *(uint32_t*)(sm + o8 + 16);
            ql[0] = *(uint32_t*)(sm + 18432 + o);
            ql[1] = *(uint32_t*)(sm + 18432 + o8);
            ql[2] = *(uint32_t*)(sm + 18432 + o + 16);
            ql[3] = *(uint32_t*)(sm + 18432 + o8 + 16);
            #pragma unroll
            for (int nt = 0; nt < 16; nt++) {
                uint32_t ko = (nt * 8 + g) * 144 + kc * 32 + t4 * 4;
                uint32_t bh0 = *(uint32_t*)(kp + ko);
                uint32_t bh1 = *(uint32_t*)(kp + ko + 16);
                uint32_t bl0 = *(uint32_t*)(kp + 18432 + ko);
                uint32_t bl1 = *(uint32_t*)(kp + 18432 + ko + 16);
                mma16816(sa[nt], qh, bh0, bh1);
                mma16816h(sa16[nt], qh, bl0, bl1);
                mma16816h(sa16[nt], ql, bh0, bh1);
            }
        }
        #pragma unroll
        for (int nt = 0; nt < 16; nt++) fold2(sa[nt], sa16[nt]);

        // ---- bias + online softmax ----
        float m0n = m0, m1n = m1;
        #pragma unroll
        for (int nt = 0; nt < 16; nt++) {
            int base = nt * 8 + t4 * 2 - (wid * 16 + g) + 127;
            sa[nt][0] += bsm[base];
            sa[nt][1] += bsm[base + 1];
            sa[nt][2] += bsm[base - 8];
            sa[nt][3] += bsm[base - 7];
            m0n = fmaxf(m0n, fmaxf(sa[nt][0], sa[nt][1]));
            m1n = fmaxf(m1n, fmaxf(sa[nt][2], sa[nt][3]));
        }
        m0n = fmaxf(m0n, __shfl_xor_sync(0xffffffffu, m0n, 1));
        m0n = fmaxf(m0n, __shfl_xor_sync(0xffffffffu, m0n, 2));
        m1n = fmaxf(m1n, __shfl_xor_sync(0xffffffffu, m1n, 1));
        m1n = fmaxf(m1n, __shfl_xor_sync(0xffffffffu, m1n, 2));

        float sc0 = __expf(m0 - m0n), sc1 = __expf(m1 - m1n);
        float rs0 = 0.f, rs1 = 0.f;
        #pragma unroll
        for (int nt = 0; nt < 16; nt++) {
            sa[nt][0] = __expf(sa[nt][0] - m0n);
            sa[nt][1] = __expf(sa[nt][1] - m0n);
            sa[nt][2] = __expf(sa[nt][2] - m1n);
            sa[nt][3] = __expf(sa[nt][3] - m1n);
            rs0 += sa[nt][0] + sa[nt][1];
            rs1 += sa[nt][2] + sa[nt][3];
        }
        rs0 += __shfl_xor_sync(0xffffffffu, rs0, 1);
        rs0 += __shfl_xor_sync(0xffffffffu, rs0, 2);
        rs1 += __shfl_xor_sync(0xffffffffu, rs1, 1);
        rs1 += __shfl_xor_sync(0xffffffffu, rs1, 2);
        l0 = l0 * sc0 + rs0;
        l1 = l1 * sc1 + rs1;
        m0 = m0n; m1 = m1n;
        #pragma unroll
        for (int nt = 0; nt < 8; nt++) {
            oa[nt][0] *= sc0; oa[nt][1] *= sc0;
            oa[nt][2] *= sc1; oa[nt][3] *= sc1;
        }

        // ---- O += P V (main f32-acc + corrections f16-acc, fold per kt) ----
        uint32_t oa16[8][2];
        #pragma unroll
        for (int nt = 0; nt < 8; nt++) { oa16[nt][0] = 0u; oa16[nt][1] = 0u; }

        #pragma unroll
        for (int kc = 0; kc < 8; kc++) {
            float* pA = sa[2 * kc];
            float* pB = sa[2 * kc + 1];
            uint32_t ph[4], pl[4];
            ph[0] = packhf(pA[0], pA[1]);
            ph[1] = packhf(pA[2], pA[3]);
            ph[2] = packhf(pB[0], pB[1]);
            ph[3] = packhf(pB[2], pB[3]);
            pl[0] = packhf(hflo(pA[0]), hflo(pA[1]));
            pl[1] = packhf(hflo(pA[2]), hflo(pA[3]));
            pl[2] = packhf(hflo(pB[0]), hflo(pB[1]));
            pl[3] = packhf(hflo(pB[2]), hflo(pB[3]));
            #pragma unroll
            for (int nt = 0; nt < 8; nt++) {
                uint32_t vo = (nt * 8 + g) * VSTR + kc * 32 + t4 * 4;
                uint32_t vh0 = *(uint32_t*)(vp + vo);
                uint32_t vh1 = *(uint32_t*)(vp + vo + 16);
                uint32_t vl0 = *(uint32_t*)(vp + 17408 + vo);
                uint32_t vl1 = *(uint32_t*)(vp + 17408 + vo + 16);
                mma16816(oa[nt], ph, vh0, vh1);
                mma16816h(oa16[nt], ph, vl0, vl1);
                mma16816h(oa16[nt], pl, vh0, vh1);
            }
        }
        #pragma unroll
        for (int nt = 0; nt < 8; nt++) fold2(oa[nt], oa16[nt]);
        __syncthreads();
    }

    // ---- normalize, split, store ctx ----
    float inv0 = 1.f / l0, inv1 = 1.f / l1;
    #pragma unroll
    for (int nt = 0; nt < 8; nt++) {
        size_t o0 = qbase + (size_t)(wid * 16 + g) * HD + nt * 8 + t4 * 2;
        size_t o8 = o0 + 8 * HD;
        float v0 = oa[nt][0] * inv0, v1 = oa[nt][1] * inv0;
        float v2 = oa[nt][2] * inv1, v3 = oa[nt][3] * inv1;
        *(uint32_t*)(Chi + o0) = packhf(v0, v1);
        *(uint32_t*)(Clo + o0) = packhf(hflo(v0), hflo(v1));
        *(uint32_t*)(Chi + o8) = packhf(v2, v3);
        *(uint32_t*)(Clo + o8) = packhf(hflo(v2), hflo(v3));
    }
}

// ---------------------------------------------------------------------------
// Launch
// ---------------------------------------------------------------------------
extern "C" void kernel_launch(void* const* d_in, const int* in_sizes, int n_in,
                              void* d_out, int out_size) {
    const float* X  = (const float*)d_in[0];
    const float* Wq = (const float*)d_in[1];
    const float* Wk = (const float*)d_in[2];
    const float* Wv = (const float*)d_in[3];
    const float* Wo = (const float*)d_in[4];
    const float* rb = (const float*)d_in[5];
    float* out = (float*)d_out;

    __half *Xhi, *Xlo, *WThi, *WTlo;
    __half *Qhi, *Qlo, *Khi, *Klo, *Vhi, *Vlo, *VThi, *VTlo, *Chi, *Clo;
    cudaGetSymbolAddress((void**)&Xhi, g_Xhi);
    cudaGetSymbolAddress((void**)&Xlo, g_Xlo);
    cudaGetSymbolAddress((void**)&WThi, g_WThi);
    cudaGetSymbolAddress((void**)&WTlo, g_WTlo);
    cudaGetSymbolAddress((void**)&Qhi, g_Qhi);
    cudaGetSymbolAddress((void**)&Qlo, g_Qlo);
    cudaGetSymbolAddress((void**)&Khi, g_Khi);
    cudaGetSymbolAddress((void**)&Klo, g_Klo);
    cudaGetSymbolAddress((void**)&Vhi, g_Vhi);
    cudaGetSymbolAddress((void**)&Vlo, g_Vlo);
    cudaGetSymbolAddress((void**)&VThi, g_VThi);
    cudaGetSymbolAddress((void**)&VTlo, g_VTlo);
    cudaGetSymbolAddress((void**)&Chi, g_Chi);
    cudaGetSymbolAddress((void**)&Clo, g_Clo);

    cudaFuncSetAttribute(gemm3,
                         cudaFuncAttributeMaxDynamicSharedMemorySize, GEMM_SMEM);
    cudaFuncSetAttribute(flash_mma,
                         cudaFuncAttributeMaxDynamicSharedMemorySize, FLASH_SMEM);

    bias_table_kernel<<<(HH * 4095 + 255) / 256, 256>>>(rb);
    conv_split<<<(MS * DD / 4) / 256, 256>>>(X, Xhi, Xlo);
    conv_wt4<<<dim3(DD / 32, DD / 32, 4), dim3(32, 8)>>>(Wq, Wk, Wv, Wo, WThi, WTlo);

    dim3 gg(HD / 128, MS / 128);   // (8, 32)
    gemm3<<<gg, 256, GEMM_SMEM>>>(Xhi, Xlo, WThi, WTlo,
                                  nullptr, Qhi, Qlo, 0);
    gemm3<<<gg, 256, GEMM_SMEM>>>(Xhi, Xlo, WThi + (size_t)1 * DD * HD, WTlo + (size_t)1 * DD * HD,
                                  nullptr, Khi, Klo, 0);
    gemm3<<<gg, 256, GEMM_SMEM>>>(Xhi, Xlo, WThi + (size_t)2 * DD * HD, WTlo + (size_t)2 * DD * HD,
                                  nullptr, Vhi, Vlo, 0);

    conv_vt<<<dim3(SS / 32, 2, 32), dim3(32, 8)>>>(Vhi, Vlo, VThi, VTlo);

    flash_mma<<<dim3(SS / 128, BB * HH), 256, FLASH_SMEM>>>(
        Qhi, Qlo, Khi, Klo, VThi, VTlo, Chi, Clo);

    gemm3<<<gg, 256, GEMM_SMEM>>>(Chi, Clo, WThi + (size_t)3 * DD * HD, WTlo + (size_t)3 * DD * HD,
                                  out, nullptr, nullptr, 1);
}

// round 15
// speedup vs baseline: 1.3127x; 1.1401x over previous
#include <cuda_runtime.h>
#include <cuda_fp16.h>
#include <math.h>
#include <stdint.h>

// Problem constants
#define BB 2
#define SS 2048
#define DD 1024
#define HH 16
#define DKV 64
#define MS (BB*SS)          // 4096
#define HD (HH*DKV)         // 1024

// ---------------------------------------------------------------------------
// Device scratch (allocation-free) — fp16 hi/lo splits
// ---------------------------------------------------------------------------
__device__ float g_bias[HH*4095];                 // bias[h][rel+2047]
__device__ __half g_Xhi[MS*DD], g_Xlo[MS*DD];
__device__ __half g_WThi[4][DD*HD], g_WTlo[4][DD*HD];   // WT[n][k]
__device__ __half g_Qhi[MS*HD], g_Qlo[MS*HD];
__device__ __half g_Khi[MS*HD], g_Klo[MS*HD];
__device__ __half g_Vhi[MS*HD], g_Vlo[MS*HD];
__device__ __half g_VThi[32*64*2048];             // VT[bh][dk][s] (hi only)
__device__ __half g_Chi[MS*HD], g_Clo[MS*HD];

// ---------------------------------------------------------------------------
// Helpers (compute_103 baseline: mma.sync sm_80, cp.async sm_80)
// ---------------------------------------------------------------------------
__device__ __forceinline__ void mma16816(float* c, const uint32_t* a,
                                         uint32_t b0, uint32_t b1) {
    asm volatile(
        "mma.sync.aligned.m16n8k16.row.col.f32.f16.f16.f32 "
        "{%0,%1,%2,%3}, {%4,%5,%6,%7}, {%8,%9}, {%0,%1,%2,%3};"
        : "+f"(c[0]), "+f"(c[1]), "+f"(c[2]), "+f"(c[3])
        : "r"(a[0]), "r"(a[1]), "r"(a[2]), "r"(a[3]), "r"(b0), "r"(b1));
}
// Correction terms: f16 accumulator (rate parity, but finer fold granularity)
__device__ __forceinline__ void mma16816h(uint32_t* c, const uint32_t* a,
                                          uint32_t b0, uint32_t b1) {
    asm volatile(
        "mma.sync.aligned.m16n8k16.row.col.f16.f16.f16.f16 "
        "{%0,%1}, {%2,%3,%4,%5}, {%6,%7}, {%0,%1};"
        : "+r"(c[0]), "+r"(c[1])
        : "r"(a[0]), "r"(a[1]), "r"(a[2]), "r"(a[3]), "r"(b0), "r"(b1));
}
__device__ __forceinline__ void fold2(float* c, const uint32_t* h) {
    __half2 x0 = *(const __half2*)&h[0];
    __half2 x1 = *(const __half2*)&h[1];
    c[0] += __low2float(x0); c[1] += __high2float(x0);
    c[2] += __low2float(x1); c[3] += __high2float(x1);
}
__device__ __forceinline__ uint32_t packhf(float lo, float hi) {
    __half2 r = __floats2half2_rn(lo, hi);   // .x = lo
    return *(uint32_t*)&r;
}
__device__ __forceinline__ float hflo(float x) {
    return x - __half2float(__float2half_rn(x));
}
__device__ __forceinline__ uint32_t smem_u32(const void* p) {
    uint32_t a;
    asm("{ .reg .u64 t; cvta.to.shared.u64 t, %1; cvt.u32.u64 %0, t; }"
        : "=r"(a) : "l"(p));
    return a;
}
__device__ __forceinline__ void cpa16(uint32_t d, const void* s) {
    asm volatile("cp.async.cg.shared.global [%0], [%1], 16;"
                 :: "r"(d), "l"(s) : "memory");
}
__device__ __forceinline__ void cpa4(uint32_t d, const void* s) {
    asm volatile("cp.async.ca.shared.global [%0], [%1], 4;"
                 :: "r"(d), "l"(s) : "memory");
}
#define CP_COMMIT() asm volatile("cp.async.commit_group;" ::: "memory")
#define CP_WAIT1()  asm volatile("cp.async.wait_group 1;" ::: "memory")
#define CP_WAIT0()  asm volatile("cp.async.wait_group 0;" ::: "memory")

// ---------------------------------------------------------------------------
// Bias table
// ---------------------------------------------------------------------------
__global__ void bias_table_kernel(const float* __restrict__ rel_bias) {
    int idx = blockIdx.x * blockDim.x + threadIdx.x;
    if (idx >= HH * 4095) return;
    int h   = idx / 4095;
    int rel = (idx % 4095) - 2047;
    int bucket = (rel > 0) ? 16 : 0;
    int rp = rel < 0 ? -rel : rel;
    int v;
    if (rp < 8) {
        v = rp;
    } else {
        float t = logf((float)rp * 0.125f);
        t = t / 2.772588722239781f;
        t = t * 8.0f;
        v = 8 + (int)t;
        if (v > 15) v = 15;
    }
    g_bias[idx] = rel_bias[(bucket + v) * HH + h];
}

// ---------------------------------------------------------------------------
// fp32 -> fp16 hi/lo split (X)
// ---------------------------------------------------------------------------
__global__ void conv_split(const float* __restrict__ src,
                           __half* __restrict__ hi,
                           __half* __restrict__ lo) {
    int i = blockIdx.x * blockDim.x + threadIdx.x;
    float4 v = ((const float4*)src)[i];
    __half2* hp = (__half2*)hi;
    __half2* lp = (__half2*)lo;
    float h0 = __half2float(__float2half_rn(v.x));
    float h1 = __half2float(__float2half_rn(v.y));
    float h2 = __half2float(__float2half_rn(v.z));
    float h3 = __half2float(__float2half_rn(v.w));
    hp[2*i]   = __floats2half2_rn(v.x, v.y);
    hp[2*i+1] = __floats2half2_rn(v.z, v.w);
    lp[2*i]   = __floats2half2_rn(v.x - h0, v.y - h1);
    lp[2*i+1] = __floats2half2_rn(v.z - h2, v.w - h3);
}

// ---------------------------------------------------------------------------
// Weight transpose + split, all 4 weights in one launch (grid.z picks W)
// ---------------------------------------------------------------------------
__global__ void conv_wt4(const float* __restrict__ W0, const float* __restrict__ W1,
                         const float* __restrict__ W2, const float* __restrict__ W3,
                         __half* __restrict__ thi_base,
                         __half* __restrict__ tlo_base) {
    __shared__ float t[32][33];
    int w = blockIdx.z;
    const float* W = (w == 0) ? W0 : (w == 1) ? W1 : (w == 2) ? W2 : W3;
    __half* thi = thi_base + (size_t)w * DD * HD;
    __half* tlo = tlo_base + (size_t)w * DD * HD;
    int n0 = blockIdx.x * 32, k0 = blockIdx.y * 32;
    int tx = threadIdx.x, ty = threadIdx.y;
    #pragma unroll
    for (int r = ty; r < 32; r += 8)
        t[r][tx] = W[(k0 + r) * DD + n0 + tx];
    __syncthreads();
    #pragma unroll
    for (int r = ty; r < 32; r += 8) {
        float x = t[tx][r];
        __half h = __float2half_rn(x);
        thi[(n0 + r) * DD + k0 + tx] = h;
        tlo[(n0 + r) * DD + k0 + tx] = __float2half_rn(x - __half2float(h));
    }
}

// ---------------------------------------------------------------------------
// V transpose to VT[bh][dk][s] (hi only — PV path is pure fp16)
// ---------------------------------------------------------------------------
__global__ void conv_vt(const __half* __restrict__ Vhi,
                        __half* __restrict__ VThi) {
    __shared__ __half th[32][34];
    int bh = blockIdx.z, b = bh >> 4, h = bh & 15;
    int s0 = blockIdx.x * 32, dk0 = blockIdx.y * 32;
    int tx = threadIdx.x, ty = threadIdx.y;
    #pragma unroll
    for (int r = ty; r < 32; r += 8) {
        size_t so = (size_t)(b * SS + s0 + r) * HD + h * 64 + dk0 + tx;
        th[r][tx] = Vhi[so];
    }
    __syncthreads();
    #pragma unroll
    for (int r = ty; r < 32; r += 8) {
        size_t dof = (size_t)bh * 64 * SS + (size_t)(dk0 + r) * SS + s0 + tx;
        VThi[dof] = th[tx][r];
    }
}

// ---------------------------------------------------------------------------
// 3-split fp16 GEMM (R14: KC=64, double-buffered cp.async, LDS.32 frags).
// Main hi*hi -> f32 acc; corrections hi*lo, lo*hi -> f16 acc, fold in epilogue.
// stage buf b at offset b*73728: AH+0, AL+18432, BH+36864, BL+55296
// ---------------------------------------------------------------------------
#define GEMM_SMEM 147456

__device__ __forceinline__ void g3_stage(uint32_t smb, int buf,
    const __half* __restrict__ A0, const __half* __restrict__ A1,
    const __half* __restrict__ B0, const __half* __restrict__ B1,
    int k0, int tid)
{
    uint32_t base = smb + (uint32_t)buf * 73728u;
    #pragma unroll
    for (int i = 0; i < 4; i++) {
        int v = tid + i * 256, row = v >> 3, cw = v & 7;
        size_t so = (size_t)row * 1024 + k0 + cw * 8;
        uint32_t dof = row * 144 + cw * 16;
        cpa16(base + dof,         A0 + so);
        cpa16(base + 18432 + dof, A1 + so);
        cpa16(base + 36864 + dof, B0 + so);
        cpa16(base + 55296 + dof, B1 + so);
    }
    CP_COMMIT();
}

__global__ __launch_bounds__(256) void gemm3(
    const __half* __restrict__ Ahi, const __half* __restrict__ Alo,
    const __half* __restrict__ Bhi, const __half* __restrict__ Blo,
    float* __restrict__ Cf,
    __half* __restrict__ Chi, __half* __restrict__ Clo,
    int mode)
{
    extern __shared__ char sm[];
    uint32_t smb = smem_u32(sm);
    int tid = threadIdx.x, lane = tid & 31, wid = tid >> 5;
    int g = lane >> 2, t4 = lane & 3;
    int wm = wid & 1, wn = wid >> 1;
    int n0 = blockIdx.x * 128, m0 = blockIdx.y * 128;

    const __half* A0 = Ahi + (size_t)m0 * 1024;
    const __half* A1 = Alo + (size_t)m0 * 1024;
    const __half* B0 = Bhi + (size_t)n0 * 1024;
    const __half* B1 = Blo + (size_t)n0 * 1024;

    float acc[4][4][4];
    uint32_t acc16[4][4][2];
    #pragma unroll
    for (int a = 0; a < 4; a++)
        #pragma unroll
        for (int b = 0; b < 4; b++) {
            #pragma unroll
            for (int c = 0; c < 4; c++) acc[a][b][c] = 0.f;
            acc16[a][b][0] = 0u; acc16[a][b][1] = 0u;
        }

    g3_stage(smb, 0, A0, A1, B0, B1, 0, tid);

    for (int c = 0; c < 16; c++) {
        if (c < 15) {
            g3_stage(smb, (c + 1) & 1, A0, A1, B0, B1, (c + 1) * 64, tid);
            CP_WAIT1();
        } else {
            CP_WAIT0();
        }
        __syncthreads();

        char* bp = sm + (c & 1) * 73728;
        #pragma unroll
        for (int kc = 0; kc < 4; kc++) {
            uint32_t ah[4][4], al[4][4];
            #pragma unroll
            for (int mt = 0; mt < 4; mt++) {
                uint32_t o  = (wm * 64 + mt * 16 + g) * 144 + kc * 32 + t4 * 4;
                uint32_t o8 = o + 8 * 144;
                ah[mt][0] = *(uint32_t*)(bp + o);
                ah[mt][1] = *(uint32_t*)(bp + o8);
                ah[mt][2] = *(uint32_t*)(bp + o + 16);
                ah[mt][3] = *(uint32_t*)(bp + o8 + 16);
                al[mt][0] = *(uint32_t*)(bp + 18432 + o);
                al[mt][1] = *(uint32_t*)(bp + 18432 + o8);
                al[mt][2] = *(uint32_t*)(bp + 18432 + o + 16);
                al[mt][3] = *(uint32_t*)(bp + 18432 + o8 + 16);
            }
            #pragma unroll
            for (int nt = 0; nt < 4; nt++) {
                uint32_t o = (wn * 32 + nt * 8 + g) * 144 + kc * 32 + t4 * 4;
                uint32_t bh0 = *(uint32_t*)(bp + 36864 + o);
                uint32_t bh1 = *(uint32_t*)(bp + 36864 + o + 16);
                uint32_t bl0 = *(uint32_t*)(bp + 55296 + o);
                uint32_t bl1 = *(uint32_t*)(bp + 55296 + o + 16);
                #pragma unroll
                for (int mt = 0; mt < 4; mt++)
                    mma16816(acc[mt][nt], ah[mt], bh0, bh1);
                #pragma unroll
                for (int mt = 0; mt < 4; mt++)
                    mma16816h(acc16[mt][nt], ah[mt], bl0, bl1);
                #pragma unroll
                for (int mt = 0; mt < 4; mt++)
                    mma16816h(acc16[mt][nt], al[mt], bh0, bh1);
            }
        }
        __syncthreads();
    }

    #pragma unroll
    for (int mt = 0; mt < 4; mt++) {
        #pragma unroll
        for (int nt = 0; nt < 4; nt++) {
            int row = m0 + wm * 64 + mt * 16 + g;
            int col = n0 + wn * 32 + nt * 8 + t4 * 2;
            float* c = acc[mt][nt];
            fold2(c, acc16[mt][nt]);
            if (mode) {
                *(float2*)(Cf + (size_t)row * 1024 + col)       = make_float2(c[0], c[1]);
                *(float2*)(Cf + (size_t)(row + 8) * 1024 + col) = make_float2(c[2], c[3]);
            } else {
                size_t o0 = (size_t)row * 1024 + col;
                size_t o8 = (size_t)(row + 8) * 1024 + col;
                *(uint32_t*)(Chi + o0) = packhf(c[0], c[1]);
                *(uint32_t*)(Clo + o0) = packhf(hflo(c[0]), hflo(c[1]));
                *(uint32_t*)(Chi + o8) = packhf(c[2], c[3]);
                *(uint32_t*)(Clo + o8) = packhf(hflo(c[2]), hflo(c[3]));
            }
        }
    }
}

// ---------------------------------------------------------------------------
// MMA flash attention: QK 3-split (precision-critical), PV pure fp16 (1 MMA).
// smem: Q[0,36864) | K buf b @36864+b*36864 (hi, lo+18432)
//       V buf b @110592+b*17408 (hi only; 64 rows x 272B)
//       bias buf b @145408+b*1024
// ---------------------------------------------------------------------------
#define F_K 36864
#define F_V 110592
#define F_B 145408
#define FLASH_SMEM 147456
#define VSTR 272

__device__ __forceinline__ void fl_stage(uint32_t smb, int buf,
    const __half* __restrict__ Kh, const __half* __restrict__ Kl,
    const __half* __restrict__ Vh,
    const float* __restrict__ bsrc, int tid)
{
    uint32_t kb = smb + F_K + (uint32_t)buf * 36864u;
    #pragma unroll
    for (int i = 0; i < 4; i++) {
        int v = tid + i * 256, row = v >> 3, cw = v & 7;
        size_t so = (size_t)row * HD + cw * 8;
        uint32_t dof = row * 144 + cw * 16;
        cpa16(kb + dof,         Kh + so);
        cpa16(kb + 18432 + dof, Kl + so);
    }
    uint32_t vb = smb + F_V + (uint32_t)buf * 17408u;
    #pragma unroll
    for (int i = 0; i < 4; i++) {
        int v = tid + i * 256, row = v >> 4, cw = v & 15;   // row<64
        size_t so = (size_t)row * SS + cw * 8;
        uint32_t dof = row * VSTR + cw * 16;
        cpa16(vb + dof, Vh + so);
    }
    if (tid < 255) cpa4(smb + F_B + (uint32_t)buf * 1024u + tid * 4, bsrc + tid);
    CP_COMMIT();
}

__global__ __launch_bounds__(256) void flash_mma(
    const __half* __restrict__ Qhi, const __half* __restrict__ Qlo,
    const __half* __restrict__ Khi, const __half* __restrict__ Klo,
    const __half* __restrict__ VThi,
    __half* __restrict__ Chi, __half* __restrict__ Clo)
{
    extern __shared__ char sm[];
    uint32_t smb = smem_u32(sm);
    int tid = threadIdx.x, lane = tid & 31, wid = tid >> 5;
    int g = lane >> 2, t4 = lane & 3;
    int qt = blockIdx.x;             // 0..15
    int bh = blockIdx.y;             // 0..31
    int b = bh >> 4, h = bh & 15;

    size_t qbase = ((size_t)b * SS + qt * 128) * HD + h * 64;
    const __half* Kb  = Khi + ((size_t)b * SS) * HD + h * 64;
    const __half* Kbl = Klo + ((size_t)b * SS) * HD + h * 64;
    const __half* Vb  = VThi + (size_t)bh * 64 * SS;
    const float* btab = g_bias + h * 4095 + 2047;

    // Stage Q tile hi/lo (plain loads, once)
    #pragma unroll
    for (int i = 0; i < 4; i++) {
        int v = tid + i * 256, row = v >> 3, cw = v & 7;
        size_t so = qbase + (size_t)row * HD + cw * 8;
        uint32_t dof = row * 144 + cw * 16;
        *(uint4*)(sm + dof)         = *(const uint4*)(Qhi + so);
        *(uint4*)(sm + 18432 + dof) = *(const uint4*)(Qlo + so);
    }

    fl_stage(smb, 0, Kb, Kbl, Vb, btab - qt * 128 - 127, tid);

    float m0 = -1e30f, m1 = -1e30f, l0 = 0.f, l1 = 0.f;
    float oa[8][4];
    #pragma unroll
    for (int nt = 0; nt < 8; nt++)
        #pragma unroll
        for (int c = 0; c < 4; c++) oa[nt][c] = 0.f;

    for (int kt = 0; kt < 16; kt++) {
        if (kt < 15) {
            int kn = kt + 1;
            fl_stage(smb, kn & 1,
                     Kb + (size_t)kn * 128 * HD, Kbl + (size_t)kn * 128 * HD,
                     Vb + kn * 128,
                     btab + (kn - qt) * 128 - 127, tid);
            CP_WAIT1();
        } else {
            CP_WAIT0();
        }
        __syncthreads();

        char* kp = sm + F_K + (kt & 1) * 36864;
        char* vp = sm + F_V + (kt & 1) * 17408;
        float* bsm = (float*)(sm + F_B + (kt & 1) * 1024);

        // ---- S = Q K^T (main f32-acc + corrections f16-acc) ----
        float sa[16][4];
        uint32_t sa16[16][2];
        #pragma unroll
        for (int nt = 0; nt < 16; nt++) {
            #pragma unroll
            for (int c = 0; c < 4; c++) sa[nt][c] = 0.f;
            sa16[nt][0] = 0u; sa16[nt][1] = 0u;
        }

        #pragma unroll
        for (int kc = 0; kc < 4; kc++) {
            uint32_t qh[4], ql[4];
            uint32_t o  = (wid * 16 + g) * 144 + kc * 32 + t4 * 4;
            uint32_t o8 = o + 8 * 144;
            qh[0] = *(uint32_t*)(sm + o);
            qh[1] = *(uint32_t*)(sm + o8);
            qh[2] = *(uint32_t*)(sm + o + 16);
            qh[3] = *(uint32_t*)(sm + o8 + 16);
            ql[0] = *(uint32_t*)(sm + 18432 + o);
            ql[1] = *(uint32_t*)(sm + 18432 + o8);
            ql[2] = *(uint32_t*)(sm + 18432 + o + 16);
            ql[3] = *(uint32_t*)(sm + 18432 + o8 + 16);
            #pragma unroll
            for (int nt = 0; nt < 16; nt++) {
                uint32_t ko = (nt * 8 + g) * 144 + kc * 32 + t4 * 4;
                uint32_t bh0 = *(uint32_t*)(kp + ko);
                uint32_t bh1 = *(uint32_t*)(kp + ko + 16);
                uint32_t bl0 = *(uint32_t*)(kp + 18432 + ko);
                uint32_t bl1 = *(uint32_t*)(kp + 18432 + ko + 16);
                mma16816(sa[nt], qh, bh0, bh1);
                mma16816h(sa16[nt], qh, bl0, bl1);
                mma16816h(sa16[nt], ql, bh0, bh1);
            }
        }
        #pragma unroll
        for (int nt = 0; nt < 16; nt++) fold2(sa[nt], sa16[nt]);

        // ---- bias + online softmax ----
        float m0n = m0, m1n = m1;
        #pragma unroll
        for (int nt = 0; nt < 16; nt++) {
            int base = nt * 8 + t4 * 2 - (wid * 16 + g) + 127;
            sa[nt][0] += bsm[base];
            sa[nt][1] += bsm[base + 1];
            sa[nt][2] += bsm[base - 8];
            sa[nt][3] += bsm[base - 7];
            m0n = fmaxf(m0n, fmaxf(sa[nt][0], sa[nt][1]));
            m1n = fmaxf(m1n, fmaxf(sa[nt][2], sa[nt][3]));
        }
        m0n = fmaxf(m0n, __shfl_xor_sync(0xffffffffu, m0n, 1));
        m0n = fmaxf(m0n, __shfl_xor_sync(0xffffffffu, m0n, 2));
        m1n = fmaxf(m1n, __shfl_xor_sync(0xffffffffu, m1n, 1));
        m1n = fmaxf(m1n, __shfl_xor_sync(0xffffffffu, m1n, 2));

        float sc0 = __expf(m0 - m0n), sc1 = __expf(m1 - m1n);
        float rs0 = 0.f, rs1 = 0.f;
        #pragma unroll
        for (int nt = 0; nt < 16; nt++) {
            sa[nt][0] = __expf(sa[nt][0] - m0n);
            sa[nt][1] = __expf(sa[nt][1] - m0n);
            sa[nt][2] = __expf(sa[nt][2] - m1n);
            sa[nt][3] = __expf(sa[nt][3] - m1n);
            rs0 += sa[nt][0] + sa[nt][1];
            rs1 += sa[nt][2] + sa[nt][3];
        }
        rs0 += __shfl_xor_sync(0xffffffffu, rs0, 1);
        rs0 += __shfl_xor_sync(0xffffffffu, rs0, 2);
        rs1 += __shfl_xor_sync(0xffffffffu, rs1, 1);
        rs1 += __shfl_xor_sync(0xffffffffu, rs1, 2);
        l0 = l0 * sc0 + rs0;
        l1 = l1 * sc1 + rs1;
        m0 = m0n; m1 = m1n;
        #pragma unroll
        for (int nt = 0; nt < 8; nt++) {
            oa[nt][0] *= sc0; oa[nt][1] *= sc0;
            oa[nt][2] *= sc1; oa[nt][3] *= sc1;
        }

        // ---- O += P V (pure fp16 operands, f32 acc: 1 MMA per (kc,nt)) ----
        #pragma unroll
        for (int kc = 0; kc < 8; kc++) {
            float* pA = sa[2 * kc];
            float* pB = sa[2 * kc + 1];
            uint32_t ph[4];
            ph[0] = packhf(pA[0], pA[1]);
            ph[1] = packhf(pA[2], pA[3]);
            ph[2] = packhf(pB[0], pB[1]);
            ph[3] = packhf(pB[2], pB[3]);
            #pragma unroll
            for (int nt = 0; nt < 8; nt++) {
                uint32_t vo = (nt * 8 + g) * VSTR + kc * 32 + t4 * 4;
                uint32_t vh0 = *(uint32_t*)(vp + vo);
                uint32_t vh1 = *(uint32_t*)(vp + vo + 16);
                mma16816(oa[nt], ph, vh0, vh1);
            }
        }
        __syncthreads();
    }

    // ---- normalize, split, store ctx ----
    float inv0 = 1.f / l0, inv1 = 1.f / l1;
    #pragma unroll
    for (int nt = 0; nt < 8; nt++) {
        size_t o0 = qbase + (size_t)(wid * 16 + g) * HD + nt * 8 + t4 * 2;
        size_t o8 = o0 + 8 * HD;
        float v0 = oa[nt][0] * inv0, v1 = oa[nt][1] * inv0;
        float v2 = oa[nt][2] * inv1, v3 = oa[nt][3] * inv1;
        *(uint32_t*)(Chi + o0) = packhf(v0, v1);
        *(uint32_t*)(Clo + o0) = packhf(hflo(v0), hflo(v1));
        *(uint32_t*)(Chi + o8) = packhf(v2, v3);
        *(uint32_t*)(Clo + o8) = packhf(hflo(v2), hflo(v3));
    }
}

// ---------------------------------------------------------------------------
// Launch
// ---------------------------------------------------------------------------
extern "C" void kernel_launch(void* const* d_in, const int* in_sizes, int n_in,
                              void* d_out, int out_size) {
    const float* X  = (const float*)d_in[0];
    const float* Wq = (const float*)d_in[1];
    const float* Wk = (const float*)d_in[2];
    const float* Wv = (const float*)d_in[3];
    const float* Wo = (const float*)d_in[4];
    const float* rb = (const float*)d_in[5];
    float* out = (float*)d_out;

    __half *Xhi, *Xlo, *WThi, *WTlo;
    __half *Qhi, *Qlo, *Khi, *Klo, *Vhi, *Vlo, *VThi, *Chi, *Clo;
    cudaGetSymbolAddress((void**)&Xhi, g_Xhi);
    cudaGetSymbolAddress((void**)&Xlo, g_Xlo);
    cudaGetSymbolAddress((void**)&WThi, g_WThi);
    cudaGetSymbolAddress((void**)&WTlo, g_WTlo);
    cudaGetSymbolAddress((void**)&Qhi, g_Qhi);
    cudaGetSymbolAddress((void**)&Qlo, g_Qlo);
    cudaGetSymbolAddress((void**)&Khi, g_Khi);
    cudaGetSymbolAddress((void**)&Klo, g_Klo);
    cudaGetSymbolAddress((void**)&Vhi, g_Vhi);
    cudaGetSymbolAddress((void**)&Vlo, g_Vlo);
    cudaGetSymbolAddress((void**)&VThi, g_VThi);
    cudaGetSymbolAddress((void**)&Chi, g_Chi);
    cudaGetSymbolAddress((void**)&Clo, g_Clo);

    cudaFuncSetAttribute(gemm3,
                         cudaFuncAttributeMaxDynamicSharedMemorySize, GEMM_SMEM);
    cudaFuncSetAttribute(flash_mma,
                         cudaFuncAttributeMaxDynamicSharedMemorySize, FLASH_SMEM);

    bias_table_kernel<<<(HH * 4095 + 255) / 256, 256>>>(rb);
    conv_split<<<(MS * DD / 4) / 256, 256>>>(X, Xhi, Xlo);
    conv_wt4<<<dim3(DD / 32, DD / 32, 4), dim3(32, 8)>>>(Wq, Wk, Wv, Wo, WThi, WTlo);

    dim3 gg(HD / 128, MS / 128);   // (8, 32)
    gemm3<<<gg, 256, GEMM_SMEM>>>(Xhi, Xlo, WThi, WTlo,
                                  nullptr, Qhi, Qlo, 0);
    gemm3<<<gg, 256, GEMM_SMEM>>>(Xhi, Xlo, WThi + (size_t)1 * DD * HD, WTlo + (size_t)1 * DD * HD,
                                  nullptr, Khi, Klo, 0);
    gemm3<<<gg, 256, GEMM_SMEM>>>(Xhi, Xlo, WThi + (size_t)2 * DD * HD, WTlo + (size_t)2 * DD * HD,
                                  nullptr, Vhi, Vlo, 0);

    conv_vt<<<dim3(SS / 32, 2, 32), dim3(32, 8)>>>(Vhi, VThi);

    flash_mma<<<dim3(SS / 128, BB * HH), 256, FLASH_SMEM>>>(
        Qhi, Qlo, Khi, Klo, VThi, Chi, Clo);

    gemm3<<<gg, 256, GEMM_SMEM>>>(Chi, Clo, WThi + (size_t)3 * DD * HD, WTlo + (size_t)3 * DD * HD,
                                  out, nullptr, nullptr, 1);
}